// round 15
// baseline (speedup 1.0000x reference)
#include <cuda_runtime.h>
#include <cuda_bf16.h>
#include <cstdint>
#include <cstddef>

#define Bn 16
#define Cn 64
#define Nn 2048
#define Kn 20
#define NBOT 6    // K - ceil(2K/3)
#define TSEL 22   // preselected candidates per row

// ---- scratch (static device memory; no allocations allowed) ----
static __device__ float g_pd[(size_t)Bn * Nn * Nn];      // scores 2*dot - ||xm||^2
static __device__ float g_xx[Bn * Nn];                   // squared norms
static __device__ float g_xt[(size_t)Bn * Nn * Cn];      // transposed x, (B,N,C)
static __device__ int   g_cand[Bn * Nn * TSEL];          // fp32 top-22 candidates
static __device__ int   g_idx[Bn * Nn * Kn];             // exact top-K neighbor indices
static __device__ float g_x1n[(size_t)Bn * Nn * Cn];     // smoothed features, (B,N,C)

// ---------------- packed f32x2 helpers ----------------
__device__ __forceinline__ unsigned long long pack2(float lo, float hi) {
    unsigned long long r;
    asm("mov.b64 %0, {%1, %2};" : "=l"(r) : "f"(lo), "f"(hi));
    return r;
}
__device__ __forceinline__ void unpack2(unsigned long long v, float& lo, float& hi) {
    asm("mov.b64 {%0, %1}, %2;" : "=f"(lo), "=f"(hi) : "l"(v));
}
__device__ __forceinline__ unsigned long long fma2(unsigned long long a,
                                                   unsigned long long b,
                                                   unsigned long long c) {
    unsigned long long d;
    asm("fma.rn.f32x2 %0, %1, %2, %3;" : "=l"(d) : "l"(a), "l"(b), "l"(c));
    return d;
}

// ---------------- K0: transpose x (B,C,N) -> g_xt (B,N,C), batch-split ----------------
__global__ __launch_bounds__(256) void xt_kernel(const float* __restrict__ x, int bOff) {
    __shared__ float tile[32][33];
    int b = blockIdx.z + bOff, c0 = blockIdx.y * 32, n0 = blockIdx.x * 32;
    int tx = threadIdx.x & 31, ty = threadIdx.x >> 5;
#pragma unroll
    for (int i = ty; i < 32; i += 8)
        tile[i][tx] = x[((size_t)(b * Cn + c0 + i) << 11) + n0 + tx];
    __syncthreads();
#pragma unroll
    for (int i = ty; i < 32; i += 8)
        g_xt[(size_t)((b << 11) + n0 + i) * Cn + c0 + tx] = tile[tx][i];
}

// ---------------- K1: squared norms ----------------
__global__ void xx_kernel(const float* __restrict__ x) {
    int t = blockIdx.x * blockDim.x + threadIdx.x;
    if (t >= Bn * Nn) return;
    int b = t >> 11, n = t & (Nn - 1);
    const float* xp = x + (size_t)b * Cn * Nn + n;
    float s = 0.f;
#pragma unroll
    for (int c = 0; c < Cn; c++) {
        float v = xp[(size_t)c * Nn];
        s = fmaf(v, v, s);
    }
    g_xx[t] = s;
}

// ---------------- K2a: pure pd-GEMM for ONE batch, 128x128 tile, 8x8 micro ----------------
// smem: sA 32KB | sB 32KB | sXX 512B = 66048 B
#define SM_GEMM 66048

__global__ __launch_bounds__(256, 2) void pd_gemm_kernel(const float* __restrict__ x, int b) {
    extern __shared__ char sm[];
    float (*sA)[128] = (float(*)[128])(sm);
    float (*sB)[128] = (float(*)[128])(sm + 32768);
    float* sXX       = (float*)(sm + 65536);

    int t  = threadIdx.x;
    int tx = t & 15, ty = t >> 4;
    int n0 = blockIdx.y * 128;
    int m0 = blockIdx.x * 128;
    const float* xb = x + (size_t)b * Cn * Nn;

    // A tile scaled by 2 (exact power-of-2)
#pragma unroll
    for (int p = 0; p < 8; p++) {
        int lin = t + p * 256;
        int c = lin >> 5, i4 = lin & 31;
        float4 v = *(const float4*)(xb + (size_t)c * Nn + n0 + i4 * 4);
        v.x *= 2.f; v.y *= 2.f; v.z *= 2.f; v.w *= 2.f;
        *(float4*)&sA[c][i4 * 4] = v;
    }
#pragma unroll
    for (int p = 0; p < 8; p++) {
        int lin = t + p * 256;
        int c = lin >> 5, i4 = lin & 31;
        *(float4*)&sB[c][i4 * 4] = *(const float4*)(xb + (size_t)c * Nn + m0 + i4 * 4);
    }
    if (t < 32) *(float4*)&sXX[t * 4] = *(const float4*)(g_xx + b * Nn + m0 + t * 4);
    __syncthreads();

    unsigned long long acc[2][4][4];
#pragma unroll
    for (int h = 0; h < 2; h++)
#pragma unroll
        for (int i = 0; i < 4; i++)
#pragma unroll
            for (int p = 0; p < 4; p++) acc[h][i][p] = 0ull;

#pragma unroll 8
    for (int c = 0; c < Cn; c++) {
        float4 aLo = *(float4*)&sA[c][ty * 4];
        float4 aHi = *(float4*)&sA[c][64 + ty * 4];
        ulonglong2 b0 = *(ulonglong2*)&sB[c][tx * 4];
        ulonglong2 b1 = *(ulonglong2*)&sB[c][64 + tx * 4];
        const float* al = &aLo.x;
        const float* ah = &aHi.x;
#pragma unroll
        for (int i = 0; i < 4; i++) {
            unsigned long long a0 = pack2(al[i], al[i]);
            acc[0][i][0] = fma2(b0.x, a0, acc[0][i][0]);
            acc[0][i][1] = fma2(b0.y, a0, acc[0][i][1]);
            acc[0][i][2] = fma2(b1.x, a0, acc[0][i][2]);
            acc[0][i][3] = fma2(b1.y, a0, acc[0][i][3]);
            unsigned long long a1 = pack2(ah[i], ah[i]);
            acc[1][i][0] = fma2(b0.x, a1, acc[1][i][0]);
            acc[1][i][1] = fma2(b0.y, a1, acc[1][i][1]);
            acc[1][i][2] = fma2(b1.x, a1, acc[1][i][2]);
            acc[1][i][3] = fma2(b1.y, a1, acc[1][i][3]);
        }
    }

    float4 xxLo = *(float4*)&sXX[tx * 4];
    float4 xxHi = *(float4*)&sXX[64 + tx * 4];

#pragma unroll
    for (int h = 0; h < 2; h++) {
#pragma unroll
        for (int i = 0; i < 4; i++) {
            float s0, s1, s2, s3, s4, s5, s6, s7;
            unpack2(acc[h][i][0], s0, s1);
            unpack2(acc[h][i][1], s2, s3);
            unpack2(acc[h][i][2], s4, s5);
            unpack2(acc[h][i][3], s6, s7);
            s0 -= xxLo.x; s1 -= xxLo.y; s2 -= xxLo.z; s3 -= xxLo.w;
            s4 -= xxHi.x; s5 -= xxHi.y; s6 -= xxHi.z; s7 -= xxHi.w;
            int n = n0 + 64 * h + ty * 4 + i;
            float* op = g_pd + ((size_t)((b << 11) + n) << 11) + m0;
            *(float4*)(op + tx * 4)      = make_float4(s0, s1, s2, s3);
            *(float4*)(op + 64 + tx * 4) = make_float4(s4, s5, s6, s7);
        }
    }
}

// ---------------- K2b: warp-per-row fp32 top-22 preselect, ONE batch ----------------
__global__ __launch_bounds__(256) void topk_kernel(int b) {
    const unsigned FULL = 0xffffffffu;
    int row  = (b << 11) + (blockIdx.x << 3) + (threadIdx.x >> 5);
    int lane = threadIdx.x & 31;

    const float4* rp = (const float4*)(g_pd + ((size_t)row << 11));

    float bval = -INFINITY;   // distributed sorted list: lane j holds slot j
    int   bidx = 0;
    float thr  = -INFINITY;   // current slot-(TSEL-1) value

    for (int tc = 0; tc < 16; tc++) {
        float4 v = rp[tc * 32 + lane];
        float lmax = fmaxf(fmaxf(v.x, v.y), fmaxf(v.z, v.w));
        unsigned act = __ballot_sync(FULL, lmax > thr);
        while (act) {
            int s = __ffs((int)act) - 1;
            act &= act - 1;
            float c0 = __shfl_sync(FULL, v.x, s);
            float c1 = __shfl_sync(FULL, v.y, s);
            float c2 = __shfl_sync(FULL, v.z, s);
            float c3 = __shfl_sync(FULL, v.w, s);
            int mb = tc * 128 + s * 4;
            float cs[4] = {c0, c1, c2, c3};
#pragma unroll
            for (int i = 0; i < 4; i++) {
                float cv = cs[i];               // uniform across warp
                if (cv > thr) {                 // uniform branch
                    unsigned lt = __ballot_sync(FULL, bval < cv);
                    int pos = __ffs((int)lt) - 1;
                    float upv = __shfl_up_sync(FULL, bval, 1);
                    int   upi = __shfl_up_sync(FULL, bidx, 1);
                    if (lane > pos)      { bval = upv; bidx = upi; }
                    else if (lane == pos){ bval = cv;  bidx = mb + i; }
                    thr = __shfl_sync(FULL, bval, TSEL - 1);
                }
            }
        }
    }

    if (lane < TSEL) g_cand[row * TSEL + lane] = bidx;
}

// ---------------- K3: exact re-ranking via double-float (compensated fp32) ----------------
__device__ __forceinline__ void twosum(float a, float b, float& s, float& e) {
    s = a + b;
    float bb = s - a;
    e = (a - (s - bb)) + (b - bb);
}

__global__ __launch_bounds__(256) void refine_kernel(float* __restrict__ out, int write_idx) {
    __shared__ float sxn[8][Cn];
    const unsigned FULL = 0xffffffffu;
    int warp = threadIdx.x >> 5, lane = threadIdx.x & 31;
    int row = (blockIdx.x << 3) + warp;
    int b = row >> 11;

    const float* xn = g_xt + (size_t)row * Cn;
    sxn[warp][lane]      = xn[lane];
    sxn[warp][lane + 32] = xn[lane + 32];
    __syncwarp();

    float hi = -INFINITY, lo = 0.f;
    int m = 0x7fffffff;
    if (lane < TSEL) {
        m = g_cand[row * TSEL + lane];
        const float4* xm4 = (const float4*)(g_xt + (size_t)((b << 11) + m) * Cn);
        float sh = 0.f, se = 0.f;
#pragma unroll
        for (int q = 0; q < 16; q++) {
            float4 v = xm4[q];
            float av[4] = {sxn[warp][q * 4], sxn[warp][q * 4 + 1],
                           sxn[warp][q * 4 + 2], sxn[warp][q * 4 + 3]};
            float vv[4] = {v.x, v.y, v.z, v.w};
#pragma unroll
            for (int i = 0; i < 4; i++) {
                float a = av[i], vm = vv[i];
                float p1 = a * vm;
                float e1 = fmaf(a, vm, -p1);
                float p2 = vm * vm;
                float e2 = fmaf(vm, vm, -p2);
                float s1, t1; twosum(sh, 2.f * p1, s1, t1);
                se += t1 + 2.f * e1;
                float s2, t2; twosum(s1, -p2, s2, t2);
                se += t2 - e2;
                sh = s2;
            }
        }
        twosum(sh, se, hi, lo);
    }

    int rank = 0;
#pragma unroll
    for (int i = 0; i < TSEL; i++) {
        float vhi = __shfl_sync(FULL, hi, i);
        float vlo = __shfl_sync(FULL, lo, i);
        int   mi  = __shfl_sync(FULL, m, i);
        bool gt = (vhi > hi) || (vhi == hi && (vlo > lo || (vlo == lo && mi < m)));
        if (i != lane && gt) rank++;
    }
    if (lane < TSEL && rank < Kn) {
        g_idx[row * Kn + rank] = m;
        if (write_idx) {
            const size_t FEAT = (size_t)Bn * 2 * Cn * Nn * Kn;
            out[FEAT + (size_t)row * Kn + rank] = (float)(m + b * Nn);
        }
    }
}

// ---------------- K4: top-14-of-20 mean, (n,c)-mapped, writes (B,N,C) ----------------
__global__ __launch_bounds__(256) void smooth_kernel() {
    int t = threadIdx.x;
    int c = t & 63, nl = t >> 6;
    int bn = blockIdx.x * 4 + nl;
    int b = bn >> 11;
    const int* ip = g_idx + bn * Kn;
    const float* xtb = g_xt + ((size_t)b << 11) * Cn;

    float s = 0.f;
    float bot[NBOT];
#pragma unroll
    for (int q = 0; q < NBOT; q++) bot[q] = INFINITY;

#pragma unroll
    for (int j = 0; j < Kn; j++) {
        int m = ip[j];
        float v = xtb[(size_t)m * Cn + c];
        s += v;
        float nv = v;
#pragma unroll
        for (int q = 0; q < NBOT; q++) {
            float lo = fminf(bot[q], nv);
            float hi = fmaxf(bot[q], nv);
            bot[q] = lo; nv = hi;
        }
    }
    float bs = bot[0] + bot[1] + bot[2] + bot[3] + bot[4] + bot[5];
    g_x1n[(size_t)bn * Cn + c] = (s - bs) * (1.0f / 14.0f);
}

// ---------------- K5: feature (B, 2C, N, K), smem-staged row gathers ----------------
#define FPAD 161
__global__ __launch_bounds__(256) void feature_kernel(float* __restrict__ out) {
    __shared__ float sf[Cn][FPAD];
    __shared__ float sxe[Cn][9];
    __shared__ int   smi[160];
    int t = threadIdx.x, lane = t & 31, w = t >> 5;
    int b  = blockIdx.x >> 8;
    int n0 = (blockIdx.x & 255) * 8;
    int rowbase = (b << 11) + n0;

    if (t < 160) smi[t] = g_idx[rowbase * Kn + t];
    {
        int c = t & 63, n = t >> 6;
        sxe[c][n]     = g_xt[(size_t)(rowbase + n) * Cn + c];
        sxe[c][n + 4] = g_xt[(size_t)(rowbase + n + 4) * Cn + c];
    }
    __syncthreads();

#pragma unroll 5
    for (int q = 0; q < 20; q++) {
        int p = w * 20 + q;
        const float* r = g_x1n + (size_t)((b << 11) + smi[p]) * Cn;
        sf[lane][p]      = r[lane];
        sf[lane + 32][p] = r[lane + 32];
    }
    __syncthreads();

#pragma unroll
    for (int q = 0; q < 16; q++) {
        int ch = w * 16 + q;
        size_t base = ((size_t)(b * 128 + ch) * Nn + n0) * Kn;
        if (ch < Cn) {
#pragma unroll
            for (int r5 = 0; r5 < 5; r5++) {
                int p = lane + 32 * r5;
                int n = p / 20;
                out[base + p] = sf[ch][p] - sxe[ch][n];
            }
        } else {
#pragma unroll
            for (int r5 = 0; r5 < 5; r5++) {
                int p = lane + 32 * r5;
                int n = p / 20;
                out[base + p] = sxe[ch - Cn][n];
            }
        }
    }
}

// ---------------- launch ----------------
extern "C" void kernel_launch(void* const* d_in, const int* in_sizes, int n_in,
                              void* d_out, int out_size) {
    const float* x = nullptr;
    for (int i = 0; i < n_in; i++) {
        if (in_sizes[i] == Bn * Cn * Nn) { x = (const float*)d_in[i]; break; }
    }
    float* out = (float*)d_out;

    const long long FEAT = (long long)Bn * 2 * Cn * Nn * Kn;          // 83886080
    const long long IDXE = (long long)Bn * Nn * Kn;                   // 655360
    int write_idx = ((long long)out_size >= FEAT + IDXE) ? 1 : 0;

    cudaFuncSetAttribute(pd_gemm_kernel, cudaFuncAttributeMaxDynamicSharedMemorySize, SM_GEMM);

    xx_kernel<<<(Bn * Nn + 255) / 256, 256>>>(x);

    dim3 gt(Nn / 32, Cn / 32, Bn / 2);
    xt_kernel<<<gt, 256>>>(x, 0);
    xt_kernel<<<gt, 256>>>(x, Bn / 2);

    // per-batch interleave: topk(b) reads pd slice (16.8 MB) while L2-resident
    dim3 gg(Nn / 128, Nn / 128);                                      // (16, 16)
    for (int b = 0; b < Bn; b++) {
        pd_gemm_kernel<<<gg, 256, SM_GEMM>>>(x, b);
        topk_kernel<<<Nn / 8, 256>>>(b);
    }

    refine_kernel<<<Bn * Nn / 8, 256>>>(out, write_idx);

    smooth_kernel<<<Bn * Nn / 4, 256>>>();

    feature_kernel<<<Bn * (Nn / 8), 256>>>(out);
}

// round 16
// speedup vs baseline: 1.5170x; 1.5170x over previous
#include <cuda_runtime.h>
#include <cuda_bf16.h>
#include <cstdint>
#include <cstddef>

#define Bn 16
#define Cn 64
#define Nn 2048
#define Kn 20
#define NBOT 6    // K - ceil(2K/3)
#define TSEL 22   // preselected candidates per row
#define BCHUNK 4  // batches per gemm/topk chunk (4*16.8MB = 67MB, L2-resident)

// ---- scratch (static device memory; no allocations allowed) ----
static __device__ float g_pd[(size_t)Bn * Nn * Nn];      // scores 2*dot - ||xm||^2
static __device__ float g_xx[Bn * Nn];                   // squared norms
static __device__ float g_xt[(size_t)Bn * Nn * Cn];      // transposed x, (B,N,C)
static __device__ int   g_cand[Bn * Nn * TSEL];          // fp32 top-22 candidates
static __device__ int   g_idx[Bn * Nn * Kn];             // exact top-K neighbor indices
static __device__ float g_x1n[(size_t)Bn * Nn * Cn];     // smoothed features, (B,N,C)

// ---------------- packed f32x2 helpers ----------------
__device__ __forceinline__ unsigned long long pack2(float lo, float hi) {
    unsigned long long r;
    asm("mov.b64 %0, {%1, %2};" : "=l"(r) : "f"(lo), "f"(hi));
    return r;
}
__device__ __forceinline__ void unpack2(unsigned long long v, float& lo, float& hi) {
    asm("mov.b64 {%0, %1}, %2;" : "=f"(lo), "=f"(hi) : "l"(v));
}
__device__ __forceinline__ unsigned long long fma2(unsigned long long a,
                                                   unsigned long long b,
                                                   unsigned long long c) {
    unsigned long long d;
    asm("fma.rn.f32x2 %0, %1, %2, %3;" : "=l"(d) : "l"(a), "l"(b), "l"(c));
    return d;
}

// ---------------- K0: transpose x (B,C,N) -> g_xt (B,N,C), batch-split ----------------
__global__ __launch_bounds__(256) void xt_kernel(const float* __restrict__ x, int bOff) {
    __shared__ float tile[32][33];
    int b = blockIdx.z + bOff, c0 = blockIdx.y * 32, n0 = blockIdx.x * 32;
    int tx = threadIdx.x & 31, ty = threadIdx.x >> 5;
#pragma unroll
    for (int i = ty; i < 32; i += 8)
        tile[i][tx] = x[((size_t)(b * Cn + c0 + i) << 11) + n0 + tx];
    __syncthreads();
#pragma unroll
    for (int i = ty; i < 32; i += 8)
        g_xt[(size_t)((b << 11) + n0 + i) * Cn + c0 + tx] = tile[tx][i];
}

// ---------------- K1: squared norms ----------------
__global__ void xx_kernel(const float* __restrict__ x) {
    int t = blockIdx.x * blockDim.x + threadIdx.x;
    if (t >= Bn * Nn) return;
    int b = t >> 11, n = t & (Nn - 1);
    const float* xp = x + (size_t)b * Cn * Nn + n;
    float s = 0.f;
#pragma unroll
    for (int c = 0; c < Cn; c++) {
        float v = xp[(size_t)c * Nn];
        s = fmaf(v, v, s);
    }
    g_xx[t] = s;
}

// ---------------- K2a: pd-GEMM for BCHUNK batches, 128x128 tile, 8x8 micro ----------------
// smem: sA 32KB | sB 32KB | sXX 512B = 66048 B
#define SM_GEMM 66048

__global__ __launch_bounds__(256, 2) void pd_gemm_kernel(const float* __restrict__ x, int bOff) {
    extern __shared__ char sm[];
    float (*sA)[128] = (float(*)[128])(sm);
    float (*sB)[128] = (float(*)[128])(sm + 32768);
    float* sXX       = (float*)(sm + 65536);

    int t  = threadIdx.x;
    int tx = t & 15, ty = t >> 4;
    int b  = blockIdx.z + bOff;
    int n0 = blockIdx.y * 128;
    int m0 = blockIdx.x * 128;
    const float* xb = x + (size_t)b * Cn * Nn;

    // A tile scaled by 2 (exact power-of-2)
#pragma unroll
    for (int p = 0; p < 8; p++) {
        int lin = t + p * 256;
        int c = lin >> 5, i4 = lin & 31;
        float4 v = *(const float4*)(xb + (size_t)c * Nn + n0 + i4 * 4);
        v.x *= 2.f; v.y *= 2.f; v.z *= 2.f; v.w *= 2.f;
        *(float4*)&sA[c][i4 * 4] = v;
    }
#pragma unroll
    for (int p = 0; p < 8; p++) {
        int lin = t + p * 256;
        int c = lin >> 5, i4 = lin & 31;
        *(float4*)&sB[c][i4 * 4] = *(const float4*)(xb + (size_t)c * Nn + m0 + i4 * 4);
    }
    if (t < 32) *(float4*)&sXX[t * 4] = *(const float4*)(g_xx + b * Nn + m0 + t * 4);
    __syncthreads();

    unsigned long long acc[2][4][4];
#pragma unroll
    for (int h = 0; h < 2; h++)
#pragma unroll
        for (int i = 0; i < 4; i++)
#pragma unroll
            for (int p = 0; p < 4; p++) acc[h][i][p] = 0ull;

#pragma unroll 8
    for (int c = 0; c < Cn; c++) {
        float4 aLo = *(float4*)&sA[c][ty * 4];
        float4 aHi = *(float4*)&sA[c][64 + ty * 4];
        ulonglong2 b0 = *(ulonglong2*)&sB[c][tx * 4];
        ulonglong2 b1 = *(ulonglong2*)&sB[c][64 + tx * 4];
        const float* al = &aLo.x;
        const float* ah = &aHi.x;
#pragma unroll
        for (int i = 0; i < 4; i++) {
            unsigned long long a0 = pack2(al[i], al[i]);
            acc[0][i][0] = fma2(b0.x, a0, acc[0][i][0]);
            acc[0][i][1] = fma2(b0.y, a0, acc[0][i][1]);
            acc[0][i][2] = fma2(b1.x, a0, acc[0][i][2]);
            acc[0][i][3] = fma2(b1.y, a0, acc[0][i][3]);
            unsigned long long a1 = pack2(ah[i], ah[i]);
            acc[1][i][0] = fma2(b0.x, a1, acc[1][i][0]);
            acc[1][i][1] = fma2(b0.y, a1, acc[1][i][1]);
            acc[1][i][2] = fma2(b1.x, a1, acc[1][i][2]);
            acc[1][i][3] = fma2(b1.y, a1, acc[1][i][3]);
        }
    }

    float4 xxLo = *(float4*)&sXX[tx * 4];
    float4 xxHi = *(float4*)&sXX[64 + tx * 4];

#pragma unroll
    for (int h = 0; h < 2; h++) {
#pragma unroll
        for (int i = 0; i < 4; i++) {
            float s0, s1, s2, s3, s4, s5, s6, s7;
            unpack2(acc[h][i][0], s0, s1);
            unpack2(acc[h][i][1], s2, s3);
            unpack2(acc[h][i][2], s4, s5);
            unpack2(acc[h][i][3], s6, s7);
            s0 -= xxLo.x; s1 -= xxLo.y; s2 -= xxLo.z; s3 -= xxLo.w;
            s4 -= xxHi.x; s5 -= xxHi.y; s6 -= xxHi.z; s7 -= xxHi.w;
            int n = n0 + 64 * h + ty * 4 + i;
            float* op = g_pd + ((size_t)((b << 11) + n) << 11) + m0;
            *(float4*)(op + tx * 4)      = make_float4(s0, s1, s2, s3);
            *(float4*)(op + 64 + tx * 4) = make_float4(s4, s5, s6, s7);
        }
    }
}

// ---------------- K2b: warp-per-row fp32 top-22 preselect, BCHUNK batches ----------------
__global__ __launch_bounds__(256) void topk_kernel(int bOff) {
    const unsigned FULL = 0xffffffffu;
    int row  = (bOff << 11) + (blockIdx.x << 3) + (threadIdx.x >> 5);
    int lane = threadIdx.x & 31;

    const float4* rp = (const float4*)(g_pd + ((size_t)row << 11));

    float bval = -INFINITY;   // distributed sorted list: lane j holds slot j
    int   bidx = 0;
    float thr  = -INFINITY;   // current slot-(TSEL-1) value

    for (int tc = 0; tc < 16; tc++) {
        float4 v = rp[tc * 32 + lane];
        float lmax = fmaxf(fmaxf(v.x, v.y), fmaxf(v.z, v.w));
        unsigned act = __ballot_sync(FULL, lmax > thr);
        while (act) {
            int s = __ffs((int)act) - 1;
            act &= act - 1;
            float c0 = __shfl_sync(FULL, v.x, s);
            float c1 = __shfl_sync(FULL, v.y, s);
            float c2 = __shfl_sync(FULL, v.z, s);
            float c3 = __shfl_sync(FULL, v.w, s);
            int mb = tc * 128 + s * 4;
            float cs[4] = {c0, c1, c2, c3};
#pragma unroll
            for (int i = 0; i < 4; i++) {
                float cv = cs[i];               // uniform across warp
                if (cv > thr) {                 // uniform branch
                    unsigned lt = __ballot_sync(FULL, bval < cv);
                    int pos = __ffs((int)lt) - 1;
                    float upv = __shfl_up_sync(FULL, bval, 1);
                    int   upi = __shfl_up_sync(FULL, bidx, 1);
                    if (lane > pos)      { bval = upv; bidx = upi; }
                    else if (lane == pos){ bval = cv;  bidx = mb + i; }
                    thr = __shfl_sync(FULL, bval, TSEL - 1);
                }
            }
        }
    }

    if (lane < TSEL) g_cand[row * TSEL + lane] = bidx;
}

// ---------------- K3: exact re-ranking via double-float (compensated fp32) ----------------
__device__ __forceinline__ void twosum(float a, float b, float& s, float& e) {
    s = a + b;
    float bb = s - a;
    e = (a - (s - bb)) + (b - bb);
}

__global__ __launch_bounds__(256) void refine_kernel(float* __restrict__ out, int write_idx) {
    __shared__ float sxn[8][Cn];
    const unsigned FULL = 0xffffffffu;
    int warp = threadIdx.x >> 5, lane = threadIdx.x & 31;
    int row = (blockIdx.x << 3) + warp;
    int b = row >> 11;

    const float* xn = g_xt + (size_t)row * Cn;
    sxn[warp][lane]      = xn[lane];
    sxn[warp][lane + 32] = xn[lane + 32];
    __syncwarp();

    float hi = -INFINITY, lo = 0.f;
    int m = 0x7fffffff;
    if (lane < TSEL) {
        m = g_cand[row * TSEL + lane];
        const float4* xm4 = (const float4*)(g_xt + (size_t)((b << 11) + m) * Cn);
        float sh = 0.f, se = 0.f;
#pragma unroll
        for (int q = 0; q < 16; q++) {
            float4 v = xm4[q];
            float av[4] = {sxn[warp][q * 4], sxn[warp][q * 4 + 1],
                           sxn[warp][q * 4 + 2], sxn[warp][q * 4 + 3]};
            float vv[4] = {v.x, v.y, v.z, v.w};
#pragma unroll
            for (int i = 0; i < 4; i++) {
                float a = av[i], vm = vv[i];
                float p1 = a * vm;
                float e1 = fmaf(a, vm, -p1);
                float p2 = vm * vm;
                float e2 = fmaf(vm, vm, -p2);
                float s1, t1; twosum(sh, 2.f * p1, s1, t1);
                se += t1 + 2.f * e1;
                float s2, t2; twosum(s1, -p2, s2, t2);
                se += t2 - e2;
                sh = s2;
            }
        }
        twosum(sh, se, hi, lo);
    }

    int rank = 0;
#pragma unroll
    for (int i = 0; i < TSEL; i++) {
        float vhi = __shfl_sync(FULL, hi, i);
        float vlo = __shfl_sync(FULL, lo, i);
        int   mi  = __shfl_sync(FULL, m, i);
        bool gt = (vhi > hi) || (vhi == hi && (vlo > lo || (vlo == lo && mi < m)));
        if (i != lane && gt) rank++;
    }
    if (lane < TSEL && rank < Kn) {
        g_idx[row * Kn + rank] = m;
        if (write_idx) {
            const size_t FEAT = (size_t)Bn * 2 * Cn * Nn * Kn;
            out[FEAT + (size_t)row * Kn + rank] = (float)(m + b * Nn);
        }
    }
}

// ---------------- K4: top-14-of-20 mean, (n,c)-mapped, writes (B,N,C) ----------------
__global__ __launch_bounds__(256) void smooth_kernel() {
    int t = threadIdx.x;
    int c = t & 63, nl = t >> 6;
    int bn = blockIdx.x * 4 + nl;
    int b = bn >> 11;
    const int* ip = g_idx + bn * Kn;
    const float* xtb = g_xt + ((size_t)b << 11) * Cn;

    float s = 0.f;
    float bot[NBOT];
#pragma unroll
    for (int q = 0; q < NBOT; q++) bot[q] = INFINITY;

#pragma unroll
    for (int j = 0; j < Kn; j++) {
        int m = ip[j];
        float v = xtb[(size_t)m * Cn + c];
        s += v;
        float nv = v;
#pragma unroll
        for (int q = 0; q < NBOT; q++) {
            float lo = fminf(bot[q], nv);
            float hi = fmaxf(bot[q], nv);
            bot[q] = lo; nv = hi;
        }
    }
    float bs = bot[0] + bot[1] + bot[2] + bot[3] + bot[4] + bot[5];
    g_x1n[(size_t)bn * Cn + c] = (s - bs) * (1.0f / 14.0f);
}

// ---------------- K5: feature (B, 2C, N, K), smem-staged row gathers ----------------
#define FPAD 161
__global__ __launch_bounds__(256) void feature_kernel(float* __restrict__ out) {
    __shared__ float sf[Cn][FPAD];
    __shared__ float sxe[Cn][9];
    __shared__ int   smi[160];
    int t = threadIdx.x, lane = t & 31, w = t >> 5;
    int b  = blockIdx.x >> 8;
    int n0 = (blockIdx.x & 255) * 8;
    int rowbase = (b << 11) + n0;

    if (t < 160) smi[t] = g_idx[rowbase * Kn + t];
    {
        int c = t & 63, n = t >> 6;
        sxe[c][n]     = g_xt[(size_t)(rowbase + n) * Cn + c];
        sxe[c][n + 4] = g_xt[(size_t)(rowbase + n + 4) * Cn + c];
    }
    __syncthreads();

#pragma unroll 5
    for (int q = 0; q < 20; q++) {
        int p = w * 20 + q;
        const float* r = g_x1n + (size_t)((b << 11) + smi[p]) * Cn;
        sf[lane][p]      = r[lane];
        sf[lane + 32][p] = r[lane + 32];
    }
    __syncthreads();

#pragma unroll
    for (int q = 0; q < 16; q++) {
        int ch = w * 16 + q;
        size_t base = ((size_t)(b * 128 + ch) * Nn + n0) * Kn;
        if (ch < Cn) {
#pragma unroll
            for (int r5 = 0; r5 < 5; r5++) {
                int p = lane + 32 * r5;
                int n = p / 20;
                out[base + p] = sf[ch][p] - sxe[ch][n];
            }
        } else {
#pragma unroll
            for (int r5 = 0; r5 < 5; r5++) {
                int p = lane + 32 * r5;
                int n = p / 20;
                out[base + p] = sxe[ch - Cn][n];
            }
        }
    }
}

// ---------------- launch ----------------
extern "C" void kernel_launch(void* const* d_in, const int* in_sizes, int n_in,
                              void* d_out, int out_size) {
    const float* x = nullptr;
    for (int i = 0; i < n_in; i++) {
        if (in_sizes[i] == Bn * Cn * Nn) { x = (const float*)d_in[i]; break; }
    }
    float* out = (float*)d_out;

    const long long FEAT = (long long)Bn * 2 * Cn * Nn * Kn;          // 83886080
    const long long IDXE = (long long)Bn * Nn * Kn;                   // 655360
    int write_idx = ((long long)out_size >= FEAT + IDXE) ? 1 : 0;

    cudaFuncSetAttribute(pd_gemm_kernel, cudaFuncAttributeMaxDynamicSharedMemorySize, SM_GEMM);

    xx_kernel<<<(Bn * Nn + 255) / 256, 256>>>(x);

    dim3 gt(Nn / 32, Cn / 32, Bn / 2);
    xt_kernel<<<gt, 256>>>(x, 0);
    xt_kernel<<<gt, 256>>>(x, Bn / 2);

    // chunked interleave: 4-batch pd slice (67 MB) stays L2-resident for topk,
    // while each launch still fills the machine (1024 blocks)
    dim3 gg(Nn / 128, Nn / 128, BCHUNK);                              // (16, 16, 4)
    for (int b = 0; b < Bn; b += BCHUNK) {
        pd_gemm_kernel<<<gg, 256, SM_GEMM>>>(x, b);
        topk_kernel<<<BCHUNK * Nn / 8, 256>>>(b);
    }

    refine_kernel<<<Bn * Nn / 8, 256>>>(out, write_idx);

    smooth_kernel<<<Bn * Nn / 4, 256>>>();

    feature_kernel<<<Bn * (Nn / 8), 256>>>(out);
}

// round 17
// speedup vs baseline: 1.8479x; 1.2181x over previous
#include <cuda_runtime.h>
#include <cuda_bf16.h>
#include <cstdint>
#include <cstddef>

#define Bn 16
#define Cn 64
#define Nn 2048
#define Kn 20
#define NBOT 6    // K - ceil(2K/3)
#define TSEL 22   // preselected candidates per row

// ---- scratch (static device memory; no allocations allowed) ----
static __device__ float g_pd[(size_t)Bn * Nn * Nn];      // scores 2*dot - ||xm||^2
static __device__ float g_xx[Bn * Nn];                   // squared norms
static __device__ float g_xt[(size_t)Bn * Nn * Cn];      // transposed x, (B,N,C)
static __device__ int   g_cand[Bn * Nn * TSEL];          // fp32 top-22 candidates
static __device__ int   g_idx[Bn * Nn * Kn];             // exact top-K neighbor indices
static __device__ float g_x1n[(size_t)Bn * Nn * Cn];     // smoothed features, (B,N,C)

// ---------------- packed f32x2 helpers ----------------
__device__ __forceinline__ unsigned long long pack2(float lo, float hi) {
    unsigned long long r;
    asm("mov.b64 %0, {%1, %2};" : "=l"(r) : "f"(lo), "f"(hi));
    return r;
}
__device__ __forceinline__ void unpack2(unsigned long long v, float& lo, float& hi) {
    asm("mov.b64 {%0, %1}, %2;" : "=f"(lo), "=f"(hi) : "l"(v));
}
__device__ __forceinline__ unsigned long long fma2(unsigned long long a,
                                                   unsigned long long b,
                                                   unsigned long long c) {
    unsigned long long d;
    asm("fma.rn.f32x2 %0, %1, %2, %3;" : "=l"(d) : "l"(a), "l"(b), "l"(c));
    return d;
}

// ---------------- K0: transpose x (B,C,N) -> g_xt (B,N,C), batch-split ----------------
__global__ __launch_bounds__(256) void xt_kernel(const float* __restrict__ x, int bOff) {
    __shared__ float tile[32][33];
    int b = blockIdx.z + bOff, c0 = blockIdx.y * 32, n0 = blockIdx.x * 32;
    int tx = threadIdx.x & 31, ty = threadIdx.x >> 5;
#pragma unroll
    for (int i = ty; i < 32; i += 8)
        tile[i][tx] = x[((size_t)(b * Cn + c0 + i) << 11) + n0 + tx];
    __syncthreads();
#pragma unroll
    for (int i = ty; i < 32; i += 8)
        g_xt[(size_t)((b << 11) + n0 + i) * Cn + c0 + tx] = tile[tx][i];
}

// ---------------- K1: squared norms ----------------
__global__ void xx_kernel(const float* __restrict__ x) {
    int t = blockIdx.x * blockDim.x + threadIdx.x;
    if (t >= Bn * Nn) return;
    int b = t >> 11, n = t & (Nn - 1);
    const float* xp = x + (size_t)b * Cn * Nn + n;
    float s = 0.f;
#pragma unroll
    for (int c = 0; c < Cn; c++) {
        float v = xp[(size_t)c * Nn];
        s = fmaf(v, v, s);
    }
    g_xx[t] = s;
}

// ---------------- K2a: pd-GEMM (all batches), 128x128 tile, 8x8 micro ----------------
// smem: sA 32KB | sB 32KB | sXX 512B = 66048 B
#define SM_GEMM 66048

__global__ __launch_bounds__(256, 2) void pd_gemm_kernel(const float* __restrict__ x) {
    extern __shared__ char sm[];
    float (*sA)[128] = (float(*)[128])(sm);
    float (*sB)[128] = (float(*)[128])(sm + 32768);
    float* sXX       = (float*)(sm + 65536);

    int t  = threadIdx.x;
    int tx = t & 15, ty = t >> 4;
    int b  = blockIdx.z;
    int n0 = blockIdx.y * 128;
    int m0 = blockIdx.x * 128;
    const float* xb = x + (size_t)b * Cn * Nn;

    // A tile scaled by 2 (exact power-of-2)
#pragma unroll
    for (int p = 0; p < 8; p++) {
        int lin = t + p * 256;
        int c = lin >> 5, i4 = lin & 31;
        float4 v = *(const float4*)(xb + (size_t)c * Nn + n0 + i4 * 4);
        v.x *= 2.f; v.y *= 2.f; v.z *= 2.f; v.w *= 2.f;
        *(float4*)&sA[c][i4 * 4] = v;
    }
#pragma unroll
    for (int p = 0; p < 8; p++) {
        int lin = t + p * 256;
        int c = lin >> 5, i4 = lin & 31;
        *(float4*)&sB[c][i4 * 4] = *(const float4*)(xb + (size_t)c * Nn + m0 + i4 * 4);
    }
    if (t < 32) *(float4*)&sXX[t * 4] = *(const float4*)(g_xx + b * Nn + m0 + t * 4);
    __syncthreads();

    unsigned long long acc[2][4][4];
#pragma unroll
    for (int h = 0; h < 2; h++)
#pragma unroll
        for (int i = 0; i < 4; i++)
#pragma unroll
            for (int p = 0; p < 4; p++) acc[h][i][p] = 0ull;

#pragma unroll 8
    for (int c = 0; c < Cn; c++) {
        float4 aLo = *(float4*)&sA[c][ty * 4];
        float4 aHi = *(float4*)&sA[c][64 + ty * 4];
        ulonglong2 b0 = *(ulonglong2*)&sB[c][tx * 4];
        ulonglong2 b1 = *(ulonglong2*)&sB[c][64 + tx * 4];
        const float* al = &aLo.x;
        const float* ah = &aHi.x;
#pragma unroll
        for (int i = 0; i < 4; i++) {
            unsigned long long a0 = pack2(al[i], al[i]);
            acc[0][i][0] = fma2(b0.x, a0, acc[0][i][0]);
            acc[0][i][1] = fma2(b0.y, a0, acc[0][i][1]);
            acc[0][i][2] = fma2(b1.x, a0, acc[0][i][2]);
            acc[0][i][3] = fma2(b1.y, a0, acc[0][i][3]);
            unsigned long long a1 = pack2(ah[i], ah[i]);
            acc[1][i][0] = fma2(b0.x, a1, acc[1][i][0]);
            acc[1][i][1] = fma2(b0.y, a1, acc[1][i][1]);
            acc[1][i][2] = fma2(b1.x, a1, acc[1][i][2]);
            acc[1][i][3] = fma2(b1.y, a1, acc[1][i][3]);
        }
    }

    float4 xxLo = *(float4*)&sXX[tx * 4];
    float4 xxHi = *(float4*)&sXX[64 + tx * 4];

#pragma unroll
    for (int h = 0; h < 2; h++) {
#pragma unroll
        for (int i = 0; i < 4; i++) {
            float s0, s1, s2, s3, s4, s5, s6, s7;
            unpack2(acc[h][i][0], s0, s1);
            unpack2(acc[h][i][1], s2, s3);
            unpack2(acc[h][i][2], s4, s5);
            unpack2(acc[h][i][3], s6, s7);
            s0 -= xxLo.x; s1 -= xxLo.y; s2 -= xxLo.z; s3 -= xxLo.w;
            s4 -= xxHi.x; s5 -= xxHi.y; s6 -= xxHi.z; s7 -= xxHi.w;
            int n = n0 + 64 * h + ty * 4 + i;
            float* op = g_pd + ((size_t)((b << 11) + n) << 11) + m0;
            *(float4*)(op + tx * 4)      = make_float4(s0, s1, s2, s3);
            *(float4*)(op + 64 + tx * 4) = make_float4(s4, s5, s6, s7);
        }
    }
}

// ---------------- K2b: two-phase warp-per-row top-22 preselect ----------------
// Phase A: stash whole row in registers, lane-max, bitonic-sort the 32 maxima,
// tau = 25th-largest lane-max (provably < 22nd-largest value for distinct vals).
// Phase B: same scan/insert as before but thresholded at max(list_thr, tau) —
// final top-22 list provably identical, ~5x fewer instructions.
__global__ __launch_bounds__(256) void topk_kernel() {
    const unsigned FULL = 0xffffffffu;
    int row  = (blockIdx.x << 3) + (threadIdx.x >> 5);   // b*N + n
    int lane = threadIdx.x & 31;

    const float4* rp = (const float4*)(g_pd + ((size_t)row << 11));

    // ---- Phase A: load + lane max ----
    float4 v[16];
    float vmax = -INFINITY;
#pragma unroll
    for (int tc = 0; tc < 16; tc++) {
        v[tc] = rp[tc * 32 + lane];
        vmax = fmaxf(vmax, fmaxf(fmaxf(v[tc].x, v[tc].y), fmaxf(v[tc].z, v[tc].w)));
    }
    // bitonic ascending sort of lane maxima
    float sv = vmax;
#pragma unroll
    for (int k = 2; k <= 32; k <<= 1) {
#pragma unroll
        for (int j = k >> 1; j > 0; j >>= 1) {
            float other = __shfl_xor_sync(FULL, sv, j);
            bool asc   = ((lane & k) == 0);
            bool lower = ((lane & j) == 0);
            sv = (asc == lower) ? fminf(sv, other) : fmaxf(sv, other);
        }
    }
    float tau = __shfl_sync(FULL, sv, 7);    // ascending idx 7 = 25th largest

    // ---- Phase B: thresholded scan + exact sorted insert ----
    float bval = -INFINITY;   // distributed sorted list: lane j holds slot j
    int   bidx = 0;
    float thr  = tau;         // effective threshold = max(list 22nd, tau)

#pragma unroll
    for (int tc = 0; tc < 16; tc++) {
        float4 vv = v[tc];
        float lmax = fmaxf(fmaxf(vv.x, vv.y), fmaxf(vv.z, vv.w));
        unsigned act = __ballot_sync(FULL, lmax > thr);
        while (act) {
            int s = __ffs((int)act) - 1;
            act &= act - 1;
            float c0 = __shfl_sync(FULL, vv.x, s);
            float c1 = __shfl_sync(FULL, vv.y, s);
            float c2 = __shfl_sync(FULL, vv.z, s);
            float c3 = __shfl_sync(FULL, vv.w, s);
            int mb = tc * 128 + s * 4;
            float cs[4] = {c0, c1, c2, c3};
#pragma unroll
            for (int i = 0; i < 4; i++) {
                float cv = cs[i];               // uniform across warp
                if (cv > thr) {                 // uniform branch
                    unsigned lt = __ballot_sync(FULL, bval < cv);
                    int pos = __ffs((int)lt) - 1;
                    float upv = __shfl_up_sync(FULL, bval, 1);
                    int   upi = __shfl_up_sync(FULL, bidx, 1);
                    if (lane > pos)      { bval = upv; bidx = upi; }
                    else if (lane == pos){ bval = cv;  bidx = mb + i; }
                    thr = fmaxf(tau, __shfl_sync(FULL, bval, TSEL - 1));
                }
            }
        }
    }

    if (lane < TSEL) g_cand[row * TSEL + lane] = bidx;
}

// ---------------- K3: exact re-ranking via double-float (compensated fp32) ----------------
__device__ __forceinline__ void twosum(float a, float b, float& s, float& e) {
    s = a + b;
    float bb = s - a;
    e = (a - (s - bb)) + (b - bb);
}

__global__ __launch_bounds__(256) void refine_kernel(float* __restrict__ out, int write_idx) {
    __shared__ float sxn[8][Cn];
    const unsigned FULL = 0xffffffffu;
    int warp = threadIdx.x >> 5, lane = threadIdx.x & 31;
    int row = (blockIdx.x << 3) + warp;
    int b = row >> 11;

    const float* xn = g_xt + (size_t)row * Cn;
    sxn[warp][lane]      = xn[lane];
    sxn[warp][lane + 32] = xn[lane + 32];
    __syncwarp();

    float hi = -INFINITY, lo = 0.f;
    int m = 0x7fffffff;
    if (lane < TSEL) {
        m = g_cand[row * TSEL + lane];
        const float4* xm4 = (const float4*)(g_xt + (size_t)((b << 11) + m) * Cn);
        float sh = 0.f, se = 0.f;
#pragma unroll
        for (int q = 0; q < 16; q++) {
            float4 v = xm4[q];
            float av[4] = {sxn[warp][q * 4], sxn[warp][q * 4 + 1],
                           sxn[warp][q * 4 + 2], sxn[warp][q * 4 + 3]};
            float vv[4] = {v.x, v.y, v.z, v.w};
#pragma unroll
            for (int i = 0; i < 4; i++) {
                float a = av[i], vm = vv[i];
                float p1 = a * vm;
                float e1 = fmaf(a, vm, -p1);
                float p2 = vm * vm;
                float e2 = fmaf(vm, vm, -p2);
                float s1, t1; twosum(sh, 2.f * p1, s1, t1);
                se += t1 + 2.f * e1;
                float s2, t2; twosum(s1, -p2, s2, t2);
                se += t2 - e2;
                sh = s2;
            }
        }
        twosum(sh, se, hi, lo);
    }

    int rank = 0;
#pragma unroll
    for (int i = 0; i < TSEL; i++) {
        float vhi = __shfl_sync(FULL, hi, i);
        float vlo = __shfl_sync(FULL, lo, i);
        int   mi  = __shfl_sync(FULL, m, i);
        bool gt = (vhi > hi) || (vhi == hi && (vlo > lo || (vlo == lo && mi < m)));
        if (i != lane && gt) rank++;
    }
    if (lane < TSEL && rank < Kn) {
        g_idx[row * Kn + rank] = m;
        if (write_idx) {
            const size_t FEAT = (size_t)Bn * 2 * Cn * Nn * Kn;
            out[FEAT + (size_t)row * Kn + rank] = (float)(m + b * Nn);
        }
    }
}

// ---------------- K4: top-14-of-20 mean, (n,c)-mapped, writes (B,N,C) ----------------
__global__ __launch_bounds__(256) void smooth_kernel() {
    int t = threadIdx.x;
    int c = t & 63, nl = t >> 6;
    int bn = blockIdx.x * 4 + nl;
    int b = bn >> 11;
    const int* ip = g_idx + bn * Kn;
    const float* xtb = g_xt + ((size_t)b << 11) * Cn;

    float s = 0.f;
    float bot[NBOT];
#pragma unroll
    for (int q = 0; q < NBOT; q++) bot[q] = INFINITY;

#pragma unroll
    for (int j = 0; j < Kn; j++) {
        int m = ip[j];
        float v = xtb[(size_t)m * Cn + c];
        s += v;
        float nv = v;
#pragma unroll
        for (int q = 0; q < NBOT; q++) {
            float lo = fminf(bot[q], nv);
            float hi = fmaxf(bot[q], nv);
            bot[q] = lo; nv = hi;
        }
    }
    float bs = bot[0] + bot[1] + bot[2] + bot[3] + bot[4] + bot[5];
    g_x1n[(size_t)bn * Cn + c] = (s - bs) * (1.0f / 14.0f);
}

// ---------------- K5: feature (B, 2C, N, K), smem-staged row gathers ----------------
#define FPAD 161
__global__ __launch_bounds__(256) void feature_kernel(float* __restrict__ out) {
    __shared__ float sf[Cn][FPAD];
    __shared__ float sxe[Cn][9];
    __shared__ int   smi[160];
    int t = threadIdx.x, lane = t & 31, w = t >> 5;
    int b  = blockIdx.x >> 8;
    int n0 = (blockIdx.x & 255) * 8;
    int rowbase = (b << 11) + n0;

    if (t < 160) smi[t] = g_idx[rowbase * Kn + t];
    {
        int c = t & 63, n = t >> 6;
        sxe[c][n]     = g_xt[(size_t)(rowbase + n) * Cn + c];
        sxe[c][n + 4] = g_xt[(size_t)(rowbase + n + 4) * Cn + c];
    }
    __syncthreads();

#pragma unroll 5
    for (int q = 0; q < 20; q++) {
        int p = w * 20 + q;
        const float* r = g_x1n + (size_t)((b << 11) + smi[p]) * Cn;
        sf[lane][p]      = r[lane];
        sf[lane + 32][p] = r[lane + 32];
    }
    __syncthreads();

#pragma unroll
    for (int q = 0; q < 16; q++) {
        int ch = w * 16 + q;
        size_t base = ((size_t)(b * 128 + ch) * Nn + n0) * Kn;
        if (ch < Cn) {
#pragma unroll
            for (int r5 = 0; r5 < 5; r5++) {
                int p = lane + 32 * r5;
                int n = p / 20;
                out[base + p] = sf[ch][p] - sxe[ch][n];
            }
        } else {
#pragma unroll
            for (int r5 = 0; r5 < 5; r5++) {
                int p = lane + 32 * r5;
                int n = p / 20;
                out[base + p] = sxe[ch - Cn][n];
            }
        }
    }
}

// ---------------- launch ----------------
extern "C" void kernel_launch(void* const* d_in, const int* in_sizes, int n_in,
                              void* d_out, int out_size) {
    const float* x = nullptr;
    for (int i = 0; i < n_in; i++) {
        if (in_sizes[i] == Bn * Cn * Nn) { x = (const float*)d_in[i]; break; }
    }
    float* out = (float*)d_out;

    const long long FEAT = (long long)Bn * 2 * Cn * Nn * Kn;          // 83886080
    const long long IDXE = (long long)Bn * Nn * Kn;                   // 655360
    int write_idx = ((long long)out_size >= FEAT + IDXE) ? 1 : 0;

    cudaFuncSetAttribute(pd_gemm_kernel, cudaFuncAttributeMaxDynamicSharedMemorySize, SM_GEMM);

    xx_kernel<<<(Bn * Nn + 255) / 256, 256>>>(x);

    dim3 gt(Nn / 32, Cn / 32, Bn / 2);
    xt_kernel<<<gt, 256>>>(x, 0);
    xt_kernel<<<gt, 256>>>(x, Bn / 2);

    dim3 gg(Nn / 128, Nn / 128, Bn);                                  // (16, 16, 16)
    pd_gemm_kernel<<<gg, 256, SM_GEMM>>>(x);

    topk_kernel<<<Bn * Nn / 8, 256>>>();                              // 4096 blocks

    refine_kernel<<<Bn * Nn / 8, 256>>>(out, write_idx);

    smooth_kernel<<<Bn * Nn / 4, 256>>>();

    feature_kernel<<<Bn * (Nn / 8), 256>>>(out);
}